// round 13
// baseline (speedup 1.0000x reference)
#include <cuda_runtime.h>
#include <cstdint>
#include <math.h>

// ---------------- problem constants ----------------
#define NS    5
#define NG    70
#define NBC   40
#define HP    150          // padded grid (70 + 2*40)
#define NT    1000
#define ISZ   41           // source row (padded coords)
#define IGZ   41           // receiver row
#define SW    160          // smem row stride (floats); interior col j at x=j+4
#define CW    152          // coeff row stride
#define GPR   38           // 4-wide groups per row
#define CLUSTER 12
#define TPB   512
#define MAXNR 13
#define ROWS_S (MAXNR + 4)     // 17 smem rows per CTA (2 halo each side)

#define FIELD_FLOATS (ROWS_S * SW)                           // 2720
#define MBAR_OFF (2 * FIELD_FLOATS + 3 * MAXNR * CW + NT)    // float idx of mbars
#define SMEM_FLOATS (MBAR_OFF + 4)
#define SMEM_BYTES  (SMEM_FLOATS * 4)

__device__ float g_temp1[2 * HP * CW];
__device__ float g_temp2[2 * HP * CW];
__device__ float g_alpha[2 * HP * CW];
__device__ float g_src[NT];
__device__ float g_bsrc[2 * NS];

__constant__ int c_isx[NS]        = {40, 57, 74, 92, 109};
__constant__ int c_start[CLUSTER] = {0, 13, 26, 39, 52, 65, 78, 90, 102, 114, 126, 138};
__constant__ int c_nr[CLUSTER]    = {13, 13, 13, 13, 13, 13, 12, 12, 12, 12, 12, 12};

// ---------------- ptx helpers ----------------
__device__ __forceinline__ unsigned int smem_u32(const void* p) {
    return (unsigned int)__cvta_generic_to_shared(p);
}
__device__ __forceinline__ unsigned int mapa_u32(unsigned int a, unsigned int r) {
    unsigned int d;
    asm("mapa.shared::cluster.u32 %0, %1, %2;" : "=r"(d) : "r"(a), "r"(r));
    return d;
}
__device__ __forceinline__ unsigned int my_ctarank() {
    unsigned int r;
    asm("mov.u32 %0, %%cluster_ctarank;" : "=r"(r));
    return r;
}
__device__ __forceinline__ void st2_cluster(unsigned int a, float x, float y) {
    asm volatile("st.shared::cluster.v2.f32 [%0], {%1, %2};"
                 :: "r"(a), "f"(x), "f"(y) : "memory");
}
__device__ __forceinline__ void mbar_init(unsigned int a, unsigned int count) {
    asm volatile("mbarrier.init.shared.b64 [%0], %1;" :: "r"(a), "r"(count) : "memory");
}
__device__ __forceinline__ void mbar_arrive_remote(unsigned int a) {
    asm volatile("mbarrier.arrive.release.cluster.shared::cluster.b64 _, [%0];"
                 :: "r"(a) : "memory");
}
__device__ __forceinline__ void mbar_wait_parity(unsigned int a, int parity) {
    unsigned int done;
    asm volatile(
        "{\n\t.reg .pred p;\n\t"
        "mbarrier.try_wait.parity.acquire.cluster.shared::cta.b64 p, [%1], %2;\n\t"
        "selp.b32 %0, 1, 0, p;\n\t}"
        : "=r"(done) : "r"(a), "r"((unsigned int)parity) : "memory");
    while (!done) {
        asm volatile(
            "{\n\t.reg .pred p;\n\t"
            "mbarrier.try_wait.parity.acquire.cluster.shared::cta.b64 p, [%1], %2, 0x989680;\n\t"
            "selp.b32 %0, 1, 0, p;\n\t}"
            : "=r"(done) : "r"(a), "r"((unsigned int)parity) : "memory");
    }
}

// ---------------- init: coefficients, source wavelet, bsrc ----------------
__global__ void fwi_init(const float* __restrict__ v) {
    const int b   = blockIdx.x;          // 0..1
    const int tid = threadIdx.x;         // 256 threads
    __shared__ float red[256];

    const float* vb = v + b * 70 * 70;

    float m = 1e30f;
    for (int k = tid; k < 70 * 70; k += 256) m = fminf(m, vb[k]);
    red[tid] = m;
    __syncthreads();
    for (int s = 128; s > 0; s >>= 1) {
        if (tid < s) red[tid] = fminf(red[tid], red[tid + s]);
        __syncthreads();
    }
    const float vmin  = red[0];
    const float kappa = ((3.0f * vmin) * 16.118095650958319f) / 780.0f;

    for (int k = tid; k < HP * CW; k += 256) {
        const int i = k / CW;
        const int j = k - i * CW;
        float t1 = 0.f, t2 = 0.f, al = 0.f;
        if (j < HP) {
            const int vi = min(max(i - NBC, 0), 69);
            const int vj = min(max(j - NBC, 0), 69);
            const float vp = vb[vi * 70 + vj];
            const float a  = vp * 0.001f / 10.0f;
            al = a * a;
            float r2 = 0.f;
            int rk = -1;
            if      (j < NBC)        rk = (NBC - 1) - j;
            else if (j >= HP - NBC)  rk = j - (HP - NBC);
            else if (i < NBC)        rk = (NBC - 1) - i;
            else if (i >= HP - NBC)  rk = i - (HP - NBC);
            if (rk >= 0) {
                const float t = ((float)rk * 10.0f) / 390.0f;
                r2 = t * t;
            }
            const float kdt = (kappa * r2) * 0.001f;
            t1 = 2.0f - 5.0f * al - kdt;
            t2 = 1.0f - kdt;
        }
        const int off = b * HP * CW + k;
        g_temp1[off] = t1;
        g_temp2[off] = t2;
        g_alpha[off] = al;
    }

    if (tid < NS) {
        const int isxs = c_isx[tid];
        const int vi = min(max(ISZ  - NBC, 0), 69);
        const int vj = min(max(isxs - NBC, 0), 69);
        const float bv = vb[vi * 70 + vj] * 0.001f;
        g_bsrc[b * NS + tid] = bv * bv;
    }

    if (b == 0) {
        for (int t = tid; t < NT; t += 256) {
            float w = 0.f;
            if (t < 147) {
                const double a  = (73.0 - (double)t) * 15.0 * 0.001 * 3.141592653589793;
                const double be = a * a;
                w = (float)((1.0 - 2.0 * be) * exp(-be));
            }
            g_src[t] = w;
        }
    }
}

// ---------------- main: 12-CTA cluster per (b,s) field ----------------
__global__ void __launch_bounds__(TPB, 1)
fwi_kernel(float* __restrict__ out) {
    extern __shared__ float sm[];
    float* buf0 = sm;
    float* buf1 = sm + FIELD_FLOATS;
    float* sT1  = sm + 2 * FIELD_FLOATS;
    float* sT2  = sT1 + MAXNR * CW;
    float* sAL  = sT2 + MAXNR * CW;
    float* srcs = sAL + MAXNR * CW;

    const int tid  = threadIdx.x;
    const int cid  = blockIdx.x / CLUSTER;
    const unsigned int rank = my_ctarank();
    const int b = cid / NS, s = cid - b * NS;

    const int start = c_start[rank];
    const int nr    = c_nr[rank];
    const unsigned int rp = (rank + CLUSTER - 1) % CLUSTER;
    const unsigned int rn = (rank + 1) % CLUSTER;
    const int nr_p = c_nr[rp];

    const unsigned int mb_u = smem_u32(sm + MBAR_OFF);
    const unsigned int b0_u = smem_u32(buf0);
    const unsigned int b1_u = smem_u32(buf1);

    // ---- init smem: zero fields, copy coeff slice + wavelet, init mbarriers ----
    for (int k = tid; k < 2 * FIELD_FLOATS; k += TPB) sm[k] = 0.f;
    {
        const float* GT1 = g_temp1 + (b * HP + start) * CW;
        const float* GT2 = g_temp2 + (b * HP + start) * CW;
        const float* GAL = g_alpha + (b * HP + start) * CW;
        const int n = nr * CW;
        for (int k = tid; k < n; k += TPB) {
            sT1[k] = GT1[k];
            sT2[k] = GT2[k];
            sAL[k] = GAL[k];
        }
        for (int k = tid; k < NT; k += TPB) srcs[k] = g_src[k];
    }
    if (tid == 0) {
        mbar_init(mb_u + 0, 2);   // full[buffer 0]: 2 neighbor arrivals per use
        mbar_init(mb_u + 8, 2);   // full[buffer 1]
        asm volatile("fence.mbarrier_init.release.cluster;" ::: "memory");
    }
    __syncthreads();

    // ---- per-thread geometry: boundary rows mapped to slots 0..3 (warps 0-4) ----
    const int slot = tid / GPR;
    const int g    = tid - slot * GPR;
    const int j0   = g * 4;
    const bool active = (slot < nr);
    int i;
    if (slot < 2)      i = slot;            // rows 0,1        (push to prev)
    else if (slot < 4) i = nr - 4 + slot;   // rows nr-2,nr-1  (push to next)
    else               i = slot - 2;        // interior rows 2..nr-3

    const int boff = (i + 2) * SW + j0;  // float index of x=j0 (logical j0-4)
    const int cb   = i * CW + j0;

    const bool pushP = active && (slot < 2);
    const bool pushN = active && (slot >= 2) && (slot < 4);
    const bool lastg = (g == GPR - 1);
    const unsigned int ppo = (unsigned int)(((nr_p + 2 + i) * SW + j0 + 4) * 4);
    const unsigned int pno = (unsigned int)(((i - (nr - 2)) * SW + j0 + 4) * 4);

    // hoist loop-invariant coefficients into registers
    float4 t1v = make_float4(0, 0, 0, 0);
    float4 t2v = t1v, alv = t1v;
    if (active) {
        t1v = *(const float4*)(sT1 + cb);
        t2v = *(const float4*)(sT2 + cb);
        alv = *(const float4*)(sAL + cb);
    }

    asm volatile("barrier.cluster.arrive.aligned;" ::: "memory");
    asm volatile("barrier.cluster.wait.aligned;"   ::: "memory");

    // remote bases (per target buffer)
    const unsigned int prevB0 = mapa_u32(b0_u, rp), prevB1 = mapa_u32(b1_u, rp);
    const unsigned int nextB0 = mapa_u32(b0_u, rn), nextB1 = mapa_u32(b1_u, rn);
    const unsigned int mprev0 = mapa_u32(mb_u, rp), mprev1 = mapa_u32(mb_u + 8, rp);
    const unsigned int mnext0 = mapa_u32(mb_u, rn), mnext1 = mapa_u32(mb_u + 8, rn);

    const int  li_src  = (ISZ >= start && ISZ < start + nr) ? (ISZ - start) : -1000;
    const int  isxs    = c_isx[s];
    const int  dsel    = isxs - j0;
    const bool srcflag = active && (i == li_src) && (dsel >= 0) && (dsel < 4);

    const bool recflag = (IGZ >= start && IGZ < start + nr) && (tid < NG);
    const int  rec_off = (IGZ - start + 2) * SW + 4 + NBC + tid;
    const float bsrcv = g_bsrc[b * NS + s];
    float* __restrict__ orow = out + (size_t)(b * NS + s) * NT * NG;

    const float C2v = (float)( 4.0 / 3.0);
    const float C3v = (float)(-1.0 / 12.0);

    const float* pcur = buf1;   // p(t) in smem (halo/z rows)
    float*       pnew = buf0;   // store target; pushes target buffer W=t&1

    // register time-cache of this thread's 4 cells: cur = p(t), old = p(t-1)
    float cur0 = 0.f, cur1 = 0.f, cur2 = 0.f, cur3 = 0.f;
    float old0 = 0.f, old1 = 0.f, old2 = 0.f, old3 = 0.f;

    for (int t = 0; t < NT; ++t) {
        const int W = t & 1;
        const float srcval = bsrcv * srcs[t];

        if (active) {
            // x-edge cells of center row p(t): left j0-2,j0-1 and right j0+4,j0+5
            const float2 eL = *(const float2*)(pcur + boff + 2);
            const float2 eR = *(const float2*)(pcur + boff + 8);
            // z-neighbor rows (incl. halo rows pushed by neighbors)
            const float4 zm2 = *(const float4*)(pcur + boff - 2 * SW + 4);
            const float4 zm1 = *(const float4*)(pcur + boff -     SW + 4);
            const float4 zp1 = *(const float4*)(pcur + boff +     SW + 4);
            const float4 zp2 = *(const float4*)(pcur + boff + 2 * SW + 4);

            float cc6 = cur2, cc7 = cur3;
            if (lastg) {
                const float2 eM = *(const float2*)(pcur + boff + 6);
                cc6 = eM.x; cc7 = eM.y;
            }
            const float cc2 = eL.x, cc3 = eL.y;
            const float cc4 = cur0, cc5 = cur1;
            const float cc8 = eR.x, cc9 = eR.y;

            const float l0 = C2v * (cc3 + cc5 + zm1.x + zp1.x)
                           + C3v * (cc2 + cc6 + zm2.x + zp2.x);
            const float l1 = C2v * (cc4 + cc6 + zm1.y + zp1.y)
                           + C3v * (cc3 + cc7 + zm2.y + zp2.y);
            const float l2 = C2v * (cc5 + cc7 + zm1.z + zp1.z)
                           + C3v * (cc4 + cc8 + zm2.z + zp2.z);
            const float l3 = C2v * (cc6 + cc8 + zm1.w + zp1.w)
                           + C3v * (cc5 + cc9 + zm2.w + zp2.w);

            float n0 = t1v.x * cc4 - t2v.x * old0 + alv.x * l0;
            float n1 = t1v.y * cc5 - t2v.y * old1 + alv.y * l1;
            float n2 = t1v.z * cc6 - t2v.z * old2 + alv.z * l2;
            float n3 = t1v.w * cc7 - t2v.w * old3 + alv.w * l3;

            if (srcflag) {
                if      (dsel == 0) n0 += srcval;
                else if (dsel == 1) n1 += srcval;
                else if (dsel == 2) n2 += srcval;
                else                n3 += srcval;
            }

            if (lastg) {
                // only j=148,149 real; also write left x-mirror (x2,x3)
                *(float2*)(pnew + boff + 4)      = make_float2(n0, n1);
                *(float2*)(pnew + boff - j0 + 2) = make_float2(n0, n1);
            } else {
                *(float4*)(pnew + boff + 4) = make_float4(n0, n1, n2, n3);
                if (g == 0)  // right x-mirror (x154,x155) <- j=0,1
                    *(float2*)(pnew + boff + 154) = make_float2(n0, n1);
            }

            // boundary rows: push into neighbor halo (buffer W)
            if (pushP) {
                const unsigned int a = (W ? prevB1 : prevB0) + ppo;
                st2_cluster(a,     n0, n1);
                st2_cluster(a + 8, n2, n3);
            } else if (pushN) {
                const unsigned int a = (W ? nextB1 : nextB0) + pno;
                st2_cluster(a,     n0, n1);
                st2_cluster(a + 8, n2, n3);
            }

            // rotate register time-cache
            old0 = cur0; old1 = cur1; old2 = cur2; old3 = cur3;
            cur0 = n0;   cur1 = n1;   cur2 = n2;   cur3 = n3;
        }

        // early elected arrives: warps 0-5 rendezvous (covers all pushers and
        // all halo readers), then signal both neighbors while interior warps
        // are still finishing phase A.
        if (tid < 192) {
            asm volatile("bar.sync 1, 192;" ::: "memory");
            if (tid == 0)       mbar_arrive_remote(W ? mprev1 : mprev0);
            else if (tid == 32) mbar_arrive_remote(W ? mnext1 : mnext0);
        }

        __syncthreads();   // local pnew writes visible CTA-wide

        if (recflag) orow[t * NG + tid] = pnew[rec_off];

        // wait: both neighbors' step-t pushes into my buffer-W halo visible
        mbar_wait_parity(mb_u + 8 * W, (t >> 1) & 1);

        float* tmp = pnew; pnew = (float*)pcur; pcur = tmp;
    }

    asm volatile("barrier.cluster.arrive.aligned;" ::: "memory");
    asm volatile("barrier.cluster.wait.aligned;"   ::: "memory");
}

// ---------------- launch ----------------
extern "C" void kernel_launch(void* const* d_in, const int* in_sizes, int n_in,
                              void* d_out, int out_size) {
    const float* v = (const float*)d_in[0];
    float* out = (float*)d_out;

    cudaFuncSetAttribute(fwi_kernel, cudaFuncAttributeMaxDynamicSharedMemorySize,
                         SMEM_BYTES);
    // cluster size 12 > 8 requires the non-portable opt-in
    cudaFuncSetAttribute(fwi_kernel,
                         cudaFuncAttributeNonPortableClusterSizeAllowed, 1);

    fwi_init<<<2, 256>>>(v);

    cudaLaunchConfig_t cfg = {};
    cfg.gridDim  = dim3(2 * NS * CLUSTER, 1, 1);
    cfg.blockDim = dim3(TPB, 1, 1);
    cfg.dynamicSmemBytes = SMEM_BYTES;
    cudaLaunchAttribute attrs[1];
    attrs[0].id = cudaLaunchAttributeClusterDimension;
    attrs[0].val.clusterDim.x = CLUSTER;
    attrs[0].val.clusterDim.y = 1;
    attrs[0].val.clusterDim.z = 1;
    cfg.attrs = attrs;
    cfg.numAttrs = 1;
    cudaLaunchKernelEx(&cfg, fwi_kernel, out);
}

// round 15
// speedup vs baseline: 1.2460x; 1.2460x over previous
#include <cuda_runtime.h>
#include <cstdint>
#include <math.h>

// ---------------- problem constants ----------------
#define NS    5
#define NG    70
#define NBC   40
#define HP    150          // padded grid (70 + 2*40)
#define NT    1000
#define ISZ   41           // source row (padded coords)
#define IGZ   41           // receiver row
#define SW    160          // smem row stride (floats); interior col j at x=j+4
#define CW    152          // coeff row stride
#define GPR   38           // 4-wide groups per row
#define CLUSTER 8
#define TPB   896          // 28 warps: bands 3 + 7*3 + 4
#define MAXNR 19
#define ROWS_S (MAXNR + 4)     // 23 smem rows per CTA (2 halo each side)

#define FIELD_FLOATS (ROWS_S * SW)                           // 3680
#define MBAR_OFF (2 * FIELD_FLOATS + 3 * MAXNR * CW + NT)    // float idx of mbars
#define SMEM_FLOATS (MBAR_OFF + 8)                           // 4 x u64 mbarriers
#define SMEM_BYTES  (SMEM_FLOATS * 4)

__device__ float g_temp1[2 * HP * CW];
__device__ float g_temp2[2 * HP * CW];
__device__ float g_alpha[2 * HP * CW];
__device__ float g_src[NT];
__device__ float g_bsrc[2 * NS];

__constant__ int c_isx[NS]        = {40, 57, 74, 92, 109};
__constant__ int c_start[CLUSTER] = {0, 19, 38, 57, 76, 95, 114, 132};
__constant__ int c_nr[CLUSTER]    = {19, 19, 19, 19, 19, 19, 18, 18};

// mbar layout (byte offsets from mb_u):
//  +0  M_top[0]   +8  M_top[1]    (filled by prev CTA's band8; count 4)
//  +16 M_bot[0]   +24 M_bot[1]    (filled by next CTA's band0; count 3)

// ---------------- ptx helpers ----------------
__device__ __forceinline__ unsigned int smem_u32(const void* p) {
    return (unsigned int)__cvta_generic_to_shared(p);
}
__device__ __forceinline__ unsigned int mapa_u32(unsigned int a, unsigned int r) {
    unsigned int d;
    asm("mapa.shared::cluster.u32 %0, %1, %2;" : "=r"(d) : "r"(a), "r"(r));
    return d;
}
__device__ __forceinline__ unsigned int my_ctarank() {
    unsigned int r;
    asm("mov.u32 %0, %%cluster_ctarank;" : "=r"(r));
    return r;
}
__device__ __forceinline__ void st2_cluster(unsigned int a, float x, float y) {
    asm volatile("st.shared::cluster.v2.f32 [%0], {%1, %2};"
                 :: "r"(a), "f"(x), "f"(y) : "memory");
}
__device__ __forceinline__ void named_bar(int id, int cnt) {
    asm volatile("bar.sync %0, %1;" :: "r"(id), "r"(cnt) : "memory");
}
__device__ __forceinline__ void mbar_init(unsigned int a, unsigned int count) {
    asm volatile("mbarrier.init.shared.b64 [%0], %1;" :: "r"(a), "r"(count) : "memory");
}
__device__ __forceinline__ void mbar_arrive_remote(unsigned int a) {
    asm volatile("mbarrier.arrive.release.cluster.shared::cluster.b64 _, [%0];"
                 :: "r"(a) : "memory");
}
__device__ __forceinline__ void mbar_wait_parity(unsigned int a, int parity) {
    unsigned int done;
    asm volatile(
        "{\n\t.reg .pred p;\n\t"
        "mbarrier.try_wait.parity.acquire.cluster.shared::cta.b64 p, [%1], %2;\n\t"
        "selp.b32 %0, 1, 0, p;\n\t}"
        : "=r"(done) : "r"(a), "r"((unsigned int)parity) : "memory");
    while (!done) {
        asm volatile(
            "{\n\t.reg .pred p;\n\t"
            "mbarrier.try_wait.parity.acquire.cluster.shared::cta.b64 p, [%1], %2, 0x989680;\n\t"
            "selp.b32 %0, 1, 0, p;\n\t}"
            : "=r"(done) : "r"(a), "r"((unsigned int)parity) : "memory");
    }
}

// ---------------- init: coefficients, source wavelet, bsrc ----------------
__global__ void fwi_init(const float* __restrict__ v) {
    const int b   = blockIdx.x;
    const int tid = threadIdx.x;
    __shared__ float red[256];

    const float* vb = v + b * 70 * 70;

    float m = 1e30f;
    for (int k = tid; k < 70 * 70; k += 256) m = fminf(m, vb[k]);
    red[tid] = m;
    __syncthreads();
    for (int s = 128; s > 0; s >>= 1) {
        if (tid < s) red[tid] = fminf(red[tid], red[tid + s]);
        __syncthreads();
    }
    const float vmin  = red[0];
    const float kappa = ((3.0f * vmin) * 16.118095650958319f) / 780.0f;

    for (int k = tid; k < HP * CW; k += 256) {
        const int i = k / CW;
        const int j = k - i * CW;
        float t1 = 0.f, t2 = 0.f, al = 0.f;
        if (j < HP) {
            const int vi = min(max(i - NBC, 0), 69);
            const int vj = min(max(j - NBC, 0), 69);
            const float vp = vb[vi * 70 + vj];
            const float a  = vp * 0.001f / 10.0f;
            al = a * a;
            float r2 = 0.f;
            int rk = -1;
            if      (j < NBC)        rk = (NBC - 1) - j;
            else if (j >= HP - NBC)  rk = j - (HP - NBC);
            else if (i < NBC)        rk = (NBC - 1) - i;
            else if (i >= HP - NBC)  rk = i - (HP - NBC);
            if (rk >= 0) {
                const float t = ((float)rk * 10.0f) / 390.0f;
                r2 = t * t;
            }
            const float kdt = (kappa * r2) * 0.001f;
            t1 = 2.0f - 5.0f * al - kdt;
            t2 = 1.0f - kdt;
        }
        const int off = b * HP * CW + k;
        g_temp1[off] = t1;
        g_temp2[off] = t2;
        g_alpha[off] = al;
    }

    if (tid < NS) {
        const int isxs = c_isx[tid];
        const int vi = min(max(ISZ  - NBC, 0), 69);
        const int vj = min(max(isxs - NBC, 0), 69);
        const float bv = vb[vi * 70 + vj] * 0.001f;
        g_bsrc[b * NS + tid] = bv * bv;
    }

    if (b == 0) {
        for (int t = tid; t < NT; t += 256) {
            float w = 0.f;
            if (t < 147) {
                const double a  = (73.0 - (double)t) * 15.0 * 0.001 * 3.141592653589793;
                const double be = a * a;
                w = (float)((1.0 - 2.0 * be) * exp(-be));
            }
            g_src[t] = w;
        }
    }
}

// ---------------- main: 8-CTA cluster, wavefront row-bands ----------------
__global__ void __launch_bounds__(TPB, 1) __cluster_dims__(CLUSTER, 1, 1)
fwi_kernel(float* __restrict__ out) {
    extern __shared__ float sm[];
    float* buf0 = sm;
    float* buf1 = sm + FIELD_FLOATS;
    float* sT1  = sm + 2 * FIELD_FLOATS;
    float* sT2  = sT1 + MAXNR * CW;
    float* sAL  = sT2 + MAXNR * CW;
    float* srcs = sAL + MAXNR * CW;

    const int tid  = threadIdx.x;
    const int cid  = blockIdx.x / CLUSTER;
    const unsigned int rank = my_ctarank();
    const int b = cid / NS, s = cid - b * NS;

    const int start = c_start[rank];
    const int nr    = c_nr[rank];
    const unsigned int rp = (rank + CLUSTER - 1) & (CLUSTER - 1);
    const unsigned int rn = (rank + 1) & (CLUSTER - 1);
    const int nr_p = c_nr[rp];

    const unsigned int mb_u = smem_u32(sm + MBAR_OFF);
    const unsigned int b0_u = smem_u32(buf0);
    const unsigned int b1_u = smem_u32(buf1);

    // ---- init smem ----
    for (int k = tid; k < 2 * FIELD_FLOATS; k += TPB) sm[k] = 0.f;
    {
        const float* GT1 = g_temp1 + (b * HP + start) * CW;
        const float* GT2 = g_temp2 + (b * HP + start) * CW;
        const float* GAL = g_alpha + (b * HP + start) * CW;
        const int n = nr * CW;
        for (int k = tid; k < n; k += TPB) {
            sT1[k] = GT1[k];
            sT2[k] = GT2[k];
            sAL[k] = GAL[k];
        }
        for (int k = tid; k < NT; k += TPB) srcs[k] = g_src[k];
    }
    if (tid == 0) {
        mbar_init(mb_u + 0,  4);   // M_top[0]: prev band8 (4 warps), buffer 0
        mbar_init(mb_u + 8,  4);   // M_top[1]
        mbar_init(mb_u + 16, 3);   // M_bot[0]: next band0 (3 warps), buffer 0
        mbar_init(mb_u + 24, 3);   // M_bot[1]
        asm volatile("fence.mbarrier_init.release.cluster;" ::: "memory");
    }
    __syncthreads();

    // ---- band geometry (warp-aligned row bands) ----
    // band0: warps 0-2, rows 0-1.  bands 1..7: 3 warps each, rows 2b..2b+1.
    // band8: warps 24-27, rows 16..nr-1.
    const int w    = tid >> 5;
    const int band = (w < 3) ? 0 : (w < 24) ? (1 + (w - 3) / 3) : 8;
    const int bfw  = (band == 0) ? 0 : (band < 8) ? 3 * band : 24;
    const int lg   = tid - bfw * 32;
    const int nrowsB = (band == 8) ? 3 : 2;
    const int row  = ((band == 8) ? 16 : 2 * band) + lg / GPR;
    const int g    = lg - (lg / GPR) * GPR;
    const int j0   = g * 4;
    const bool active = (lg < nrowsB * GPR) && (row < nr);

    const int boff = (row + 2) * SW + j0;
    const int cb   = row * CW + j0;

    const bool pushP = active && (row < 2);           // band0 -> prev bottom halo
    const bool pushN = active && (row >= nr - 2);     // band8 -> next top halo
    const bool lastg = (g == GPR - 1);
    const unsigned int ppo = (unsigned int)(((nr_p + 2 + row) * SW + j0 + 4) * 4);
    const unsigned int pno = (unsigned int)(((row - (nr - 2)) * SW + j0 + 4) * 4);

    // hoisted coefficients
    float4 t1v = make_float4(0, 0, 0, 0);
    float4 t2v = t1v, alv = t1v;
    if (active) {
        t1v = *(const float4*)(sT1 + cb);
        t2v = *(const float4*)(sT2 + cb);
        alv = *(const float4*)(sAL + cb);
    }

    asm volatile("barrier.cluster.arrive.aligned;" ::: "memory");
    asm volatile("barrier.cluster.wait.aligned;"   ::: "memory");

    // remote addresses (per target buffer)
    const unsigned int prevB0 = mapa_u32(b0_u, rp), prevB1 = mapa_u32(b1_u, rp);
    const unsigned int nextB0 = mapa_u32(b0_u, rn), nextB1 = mapa_u32(b1_u, rn);
    // band0 arrives on prev's M_bot[W]; band8 arrives on next's M_top[W]
    const unsigned int aBotPrev0 = mapa_u32(mb_u + 16, rp);
    const unsigned int aBotPrev1 = mapa_u32(mb_u + 24, rp);
    const unsigned int aTopNext0 = mapa_u32(mb_u + 0,  rn);
    const unsigned int aTopNext1 = mapa_u32(mb_u + 8,  rn);

    const int  isxs    = c_isx[s];
    const int  dsel    = isxs - j0;
    const bool srcflag = active && (start + row == ISZ) && (dsel >= 0) && (dsel < 4);

    // receivers: written from registers by the owning row's threads
    const bool recband = active && (start + row == IGZ);
    const bool r0ok = recband && (j0 + 0 >= 40) && (j0 + 0 <= 109);
    const bool r1ok = recband && (j0 + 1 >= 40) && (j0 + 1 <= 109);
    const bool r2ok = recband && (j0 + 2 >= 40) && (j0 + 2 <= 109);
    const bool r3ok = recband && (j0 + 3 >= 40) && (j0 + 3 <= 109);
    const float bsrcv = g_bsrc[b * NS + s];
    float* __restrict__ orow = out + (size_t)(b * NS + s) * NT * NG + (j0 - 40);

    const float C2v = (float)( 4.0 / 3.0);
    const float C3v = (float)(-1.0 / 12.0);

    const float* pcur = buf1;   // p(t)
    float*       pnew = buf0;   // p(t+1) target; buffer W=t&1

    // register time-cache
    float cur0 = 0.f, cur1 = 0.f, cur2 = 0.f, cur3 = 0.f;
    float old0 = 0.f, old1 = 0.f, old2 = 0.f, old3 = 0.f;

    const int cntLo = (band == 8) ? 224 : 192;    // pair (band-1, band)
    const int cntHi = (band == 7) ? 224 : 192;    // pair (band, band+1)

    for (int t = 0; t < NT; ++t) {
        const int W = t & 1;
        const float srcval = bsrcv * srcs[t];

        // ---- local wavefront sync: only adjacent bands rendezvous ----
        if (band > 0) named_bar(band, cntLo);
        if (band < 8) named_bar(band + 1, cntHi);

        // ---- edge bands: wait for neighbor CTA's step t-1 pushes (buffer (t-1)&1) ----
        if (t > 0) {
            const int Wp = (t - 1) & 1;
            const int par = ((t - 1) >> 1) & 1;
            if (band == 0)      mbar_wait_parity(mb_u + 8 * Wp, par);
            else if (band == 8) mbar_wait_parity(mb_u + 16 + 8 * Wp, par);
        }

        if (active) {
            const float2 eL = *(const float2*)(pcur + boff + 2);
            const float2 eR = *(const float2*)(pcur + boff + 8);
            const float4 zm2 = *(const float4*)(pcur + boff - 2 * SW + 4);
            const float4 zm1 = *(const float4*)(pcur + boff -     SW + 4);
            const float4 zp1 = *(const float4*)(pcur + boff +     SW + 4);
            const float4 zp2 = *(const float4*)(pcur + boff + 2 * SW + 4);

            float cc6 = cur2, cc7 = cur3;
            if (lastg) {
                const float2 eM = *(const float2*)(pcur + boff + 6);
                cc6 = eM.x; cc7 = eM.y;
            }
            const float cc2 = eL.x, cc3 = eL.y;
            const float cc4 = cur0, cc5 = cur1;
            const float cc8 = eR.x, cc9 = eR.y;

            const float l0 = C2v * (cc3 + cc5 + zm1.x + zp1.x)
                           + C3v * (cc2 + cc6 + zm2.x + zp2.x);
            const float l1 = C2v * (cc4 + cc6 + zm1.y + zp1.y)
                           + C3v * (cc3 + cc7 + zm2.y + zp2.y);
            const float l2 = C2v * (cc5 + cc7 + zm1.z + zp1.z)
                           + C3v * (cc4 + cc8 + zm2.z + zp2.z);
            const float l3 = C2v * (cc6 + cc8 + zm1.w + zp1.w)
                           + C3v * (cc5 + cc9 + zm2.w + zp2.w);

            float n0 = t1v.x * cc4 - t2v.x * old0 + alv.x * l0;
            float n1 = t1v.y * cc5 - t2v.y * old1 + alv.y * l1;
            float n2 = t1v.z * cc6 - t2v.z * old2 + alv.z * l2;
            float n3 = t1v.w * cc7 - t2v.w * old3 + alv.w * l3;

            if (srcflag) {
                if      (dsel == 0) n0 += srcval;
                else if (dsel == 1) n1 += srcval;
                else if (dsel == 2) n2 += srcval;
                else                n3 += srcval;
            }

            if (lastg) {
                *(float2*)(pnew + boff + 4)      = make_float2(n0, n1);
                *(float2*)(pnew + boff - j0 + 2) = make_float2(n0, n1);
            } else {
                *(float4*)(pnew + boff + 4) = make_float4(n0, n1, n2, n3);
                if (g == 0)
                    *(float2*)(pnew + boff + 154) = make_float2(n0, n1);
            }

            if (pushP) {
                const unsigned int a = (W ? prevB1 : prevB0) + ppo;
                st2_cluster(a,     n0, n1);
                st2_cluster(a + 8, n2, n3);
            } else if (pushN) {
                const unsigned int a = (W ? nextB1 : nextB0) + pno;
                st2_cluster(a,     n0, n1);
                st2_cluster(a + 8, n2, n3);
            }

            // receivers from registers (no CTA sync needed)
            if (recband) {
                float* o = orow + t * NG;
                if (r0ok) o[0] = n0;
                if (r1ok) o[1] = n1;
                if (r2ok) o[2] = n2;
                if (r3ok) o[3] = n3;
            }

            old0 = cur0; old1 = cur1; old2 = cur2; old3 = cur3;
            cur0 = n0;   cur1 = n1;   cur2 = n2;   cur3 = n3;
        }

        // ---- edge bands: per-warp arrive on the buffer-W mbar ----
        // warp program order (reads -> syncwarp -> arrive) carries both push
        // visibility and the read-before-clobber anti-dependence.
        if (band == 0) {
            __syncwarp();
            if ((tid & 31) == 0) mbar_arrive_remote(W ? aBotPrev1 : aBotPrev0);
        } else if (band == 8) {
            __syncwarp();
            if ((tid & 31) == 0) mbar_arrive_remote(W ? aTopNext1 : aTopNext0);
        }

        float* tmp = pnew; pnew = (float*)pcur; pcur = tmp;
    }

    asm volatile("barrier.cluster.arrive.aligned;" ::: "memory");
    asm volatile("barrier.cluster.wait.aligned;"   ::: "memory");
}

// ---------------- launch ----------------
extern "C" void kernel_launch(void* const* d_in, const int* in_sizes, int n_in,
                              void* d_out, int out_size) {
    const float* v = (const float*)d_in[0];
    float* out = (float*)d_out;

    cudaFuncSetAttribute(fwi_kernel, cudaFuncAttributeMaxDynamicSharedMemorySize,
                         SMEM_BYTES);

    fwi_init<<<2, 256>>>(v);
    fwi_kernel<<<2 * NS * CLUSTER, TPB, SMEM_BYTES>>>(out);
}